// round 13
// baseline (speedup 1.0000x reference)
#include <cuda_runtime.h>
#include <cuda_fp16.h>

// ---------------------------------------------------------------------------
// Mipmapped texture sampling, GB300 — fp16 DOUBLED-PAIR pyramid.
// Block x of a level row = [texel x | texel min(x+1, s-1)] = 64B, 64B-aligned.
// A bilinear x-span is therefore always ONE aligned 64B run -> exactly one
// L1 line touch per (level,row) span (was 1.25 with straddles).
// Level i (i>=1) texel = 0.25 * 2x2 of base pixels at y0 = y*2^i + 2^(i-1) - 1
// (exact algebra of align_corners=False downsample by 2^i): mips read the
// fp32 input directly, fused with the transpose in one launch.
// Sample: 4 lanes/query; lanes xs=0 compute level-l0 setup, xs=1 compute
// l1, exchanged via width-4 shuffles (halves the address-math issue load).
// y1 row is unclamped: weight is exactly 0 whenever it would clamp; row
// overrun reads the next level (valid) or the zero pad after level 7.
// ---------------------------------------------------------------------------

#define NLEV 8

// 11,184,640 pyramid halves (doubled) + 128 pad halves (one level-7 row)
__device__ __align__(16) __half g_pyr[11184768];

// level offsets in uint4 (16B) units
__constant__ int coff4[NLEV] = {
    0, 1048576, 1310720, 1376256, 1392640, 1396736, 1397760, 1398016
};

__device__ __forceinline__ unsigned f2u(float a, float b) {
    __half2 h = __floats2half2_rn(a, b);
    return *reinterpret_cast<const unsigned*>(&h);
}
__device__ __forceinline__ __half2 u2h(unsigned u) {
    return *reinterpret_cast<const __half2*>(&u);
}
__device__ __forceinline__ unsigned h2u(__half2 h) {
    return *reinterpret_cast<const unsigned*>(&h);
}
__device__ __forceinline__ float f2get(const float2& v, int j) {
    return j == 0 ? v.x : v.y;
}

// ---------------------------------------------------------------------------
// Fused prep kernel.
// Blocks [0,1024):    transpose. thread = (pixel-pair, channel-half t):
//   8 x LDG.64 plane loads -> chunks c0 (pixel 2g) and c1 (pixel 2g+1),
//   written into the doubled blocks:
//     blk(2g).first.t = c0, blk(2g).second.t = c1, blk(2g+1).first.t = c1,
//     blk(2g-1).second.t = c0 (if not row start),
//     blk(511).second.t = c1 (row end clamp).
// Blocks [1024,1707): mips. thread = (texel, channel-half): 2x2 fp32 average,
//   written to blk(x).first, blk(x-1).second, and blk(s-1).second at edge.
// ---------------------------------------------------------------------------
__global__ void k_prep(const float* __restrict__ tex) {
    const int plane = 512 * 512;
    uint4* pyr4 = reinterpret_cast<uint4*>(g_pyr);
    if (blockIdx.x < 1024) {
        int idx = blockIdx.x * blockDim.x + threadIdx.x;   // < 262144
        int t   = idx & 1;        // 0: channels 0-7, 1: channels 8-15
        int grp = idx >> 1;       // pixel pair (2g, 2g+1), same row
        const int plane2 = plane / 2;
        const float2* src = reinterpret_cast<const float2*>(tex) + (8 * t) * plane2 + grp;

        float2 v0 = __ldg(src);
        float2 v1 = __ldg(src + plane2);
        float2 v2 = __ldg(src + 2 * plane2);
        float2 v3 = __ldg(src + 3 * plane2);
        float2 v4 = __ldg(src + 4 * plane2);
        float2 v5 = __ldg(src + 5 * plane2);
        float2 v6 = __ldg(src + 6 * plane2);
        float2 v7 = __ldg(src + 7 * plane2);

        uint4 c0, c1;
        c0.x = f2u(v0.x, v1.x); c0.y = f2u(v2.x, v3.x);
        c0.z = f2u(v4.x, v5.x); c0.w = f2u(v6.x, v7.x);
        c1.x = f2u(v0.y, v1.y); c1.y = f2u(v2.y, v3.y);
        c1.z = f2u(v4.y, v5.y); c1.w = f2u(v6.y, v7.y);

        int pix = 2 * grp;                 // even pixel of the pair
        int x   = pix & 511;               // x within row
        uint4* blk = pyr4 + pix * 4;       // block(pix): 4 uint4 per block
        blk[t]     = c0;                   // blk(x).first.t
        blk[2 + t] = c1;                   // blk(x).second.t  (= texel x+1)
        blk[4 + t] = c1;                   // blk(x+1).first.t
        if (x > 0)    blk[-2 + t] = c0;    // blk(x-1).second.t (= texel x)
        if (x == 510) blk[6 + t]  = c1;    // blk(511).second.t (clamp)
    } else {
        int idx = (blockIdx.x - 1024) * blockDim.x + threadIdx.x;
        if (idx >= 2 * 87376) return;
        int t   = idx & 1;
        int rem = idx >> 1;

        int l = 1;
#pragma unroll
        for (int i = 1; i < NLEV; i++) {
            int np = (512 >> i) * (512 >> i);
            if (rem < np) { l = i; break; }
            rem -= np;
        }
        int s  = 512 >> l;
        int x  = rem & (s - 1);
        int y  = rem >> (9 - l);
        int sc = 1 << l;
        int x0 = x * sc + (sc >> 1) - 1;
        int y0 = y * sc + (sc >> 1) - 1;

        const float* src = tex + (8 * t) * plane + y0 * 512 + x0;
#define AVG(c) (0.25f * (__ldg(src + (c) * plane)       + __ldg(src + (c) * plane + 1) + \
                         __ldg(src + (c) * plane + 512) + __ldg(src + (c) * plane + 513)))
        float a0 = AVG(0), a1 = AVG(1), a2 = AVG(2), a3 = AVG(3);
        float a4 = AVG(4), a5 = AVG(5), a6 = AVG(6), a7 = AVG(7);
#undef AVG
        uint4 r;
        r.x = f2u(a0, a1);
        r.y = f2u(a2, a3);
        r.z = f2u(a4, a5);
        r.w = f2u(a6, a7);

        int blkbase = coff4[l] + (y * s + x) * 4;
        pyr4[blkbase + t] = r;                         // blk(x).first.t
        if (x > 0)     pyr4[blkbase - 2 + t] = r;      // blk(x-1).second.t
        if (x == s - 1) pyr4[blkbase + 2 + t] = r;     // blk(s-1).second.t
    }
}

// ---------------------------------------------------------------------------
// Sample kernel. 4 threads/query: t = 2*xs + cg.
// Lanes xs=0 compute level-l0 setup, xs=1 compute level-l1 setup; the
// (idx, rowstride, fx, fy) tuples are exchanged with width-4 shuffles.
// 4 x LDG.128 per thread; each warp-LDG touches exactly 1 line per query.
// Accumulation in half2 (HMUL2/HFMA2), xor-2 lane reduction, float4 store.
// ---------------------------------------------------------------------------
__global__ void k_sample(const float* __restrict__ uv,
                         const float* __restrict__ p,
                         float* __restrict__ out, int N) {
    int idx = blockIdx.x * blockDim.x + threadIdx.x;
    int q = idx >> 2;
    if (q >= N) return;
    int t  = idx & 3;
    int xs = t >> 1;      // 0: x0 texel / level-A duty, 1: x1 texel / level-B duty
    int cg = t & 1;       // 0: channels 0-7, 1: channels 8-15

    float2 uvq = __ldg(reinterpret_cast<const float2*>(uv) + q);
    float  pp  = __ldg(&p[q]);

    float lf = pp * (float)(NLEV - 1);
    int   l0 = min((int)lf, NLEV - 1);
    float alpha = lf - (float)l0;

    float gx = 2.0f * uvq.x - 1.0f;
    float gy = 2.0f * uvq.y - 1.0f;

    // my level: lanes xs=0 -> l0, lanes xs=1 -> l1
    int myl = min(l0 + xs, NLEV - 1);
    int s   = 512 >> myl;
    float fs = (float)(s - 1);
    float xx = fminf(fmaxf((gx + 1.0f) * 0.5f * fs, 0.0f), fs);
    float yy = fminf(fmaxf((gy + 1.0f) * 0.5f * fs, 0.0f), fs);
    int x0 = (int)xx;           // trunc == floor (xx >= 0)
    int y0 = (int)yy;
    float fx = xx - (float)x0;  // 0 exactly when x1/y1 would clamp
    float fy = yy - (float)y0;
    int myidx = coff4[myl] + (y0 * s + x0) * 4;   // uint4 units
    int myrs  = 4 * s;                            // row stride, uint4 units

    // exchange level setups within the 4-lane group
    unsigned m = __activemask();
    int   idxA = __shfl_sync(m, myidx, 0, 4);
    int   rsA  = __shfl_sync(m, myrs,  0, 4);
    float fxA  = __shfl_sync(m, fx,    0, 4);
    float fyA  = __shfl_sync(m, fy,    0, 4);
    int   idxB = __shfl_sync(m, myidx, 2, 4);
    int   rsB  = __shfl_sync(m, myrs,  2, 4);
    float fxB  = __shfl_sync(m, fx,    2, 4);
    float fyB  = __shfl_sync(m, fy,    2, 4);

    const uint4* pyr4 = reinterpret_cast<const uint4*>(g_pyr);
    // batch all 4 span loads (both levels, both rows); y1 unclamped (weight 0)
    uint4 va0 = __ldg(pyr4 + idxA + t);
    uint4 va1 = __ldg(pyr4 + idxA + rsA + t);
    uint4 vb0 = __ldg(pyr4 + idxB + t);
    uint4 vb1 = __ldg(pyr4 + idxB + rsB + t);

    float wxa = xs ? fxA : (1.0f - fxA);
    float wxb = xs ? fxB : (1.0f - fxB);
    float la  = (1.0f - alpha) * wxa;
    float lb  = alpha * wxb;
    __half2 hw0 = __float2half2_rn(la * (1.0f - fyA));
    __half2 hw1 = __float2half2_rn(la * fyA);
    __half2 hw2 = __float2half2_rn(lb * (1.0f - fyB));
    __half2 hw3 = __float2half2_rn(lb * fyB);

    // half2 accumulation: 4 HMUL2 + 12 HFMA2
    __half2 A0 = __hmul2(u2h(va0.x), hw0);
    __half2 A1 = __hmul2(u2h(va0.y), hw0);
    __half2 A2 = __hmul2(u2h(va0.z), hw0);
    __half2 A3 = __hmul2(u2h(va0.w), hw0);
    A0 = __hfma2(u2h(va1.x), hw1, A0);
    A1 = __hfma2(u2h(va1.y), hw1, A1);
    A2 = __hfma2(u2h(va1.z), hw1, A2);
    A3 = __hfma2(u2h(va1.w), hw1, A3);
    A0 = __hfma2(u2h(vb0.x), hw2, A0);
    A1 = __hfma2(u2h(vb0.y), hw2, A1);
    A2 = __hfma2(u2h(vb0.z), hw2, A2);
    A3 = __hfma2(u2h(vb0.w), hw2, A3);
    A0 = __hfma2(u2h(vb1.x), hw3, A0);
    A1 = __hfma2(u2h(vb1.y), hw3, A1);
    A2 = __hfma2(u2h(vb1.z), hw3, A2);
    A3 = __hfma2(u2h(vb1.w), hw3, A3);

    // combine x0-side and x1-side partial sums (lane ^ 2)
    A0 = __hadd2(A0, u2h(__shfl_xor_sync(m, h2u(A0), 2)));
    A1 = __hadd2(A1, u2h(__shfl_xor_sync(m, h2u(A1), 2)));
    A2 = __hadd2(A2, u2h(__shfl_xor_sync(m, h2u(A2), 2)));
    A3 = __hadd2(A3, u2h(__shfl_xor_sync(m, h2u(A3), 2)));

    // lane (xs,cg) stores float4 slot cg*2+xs: xs=0 -> ch 8cg..+3 (A0,A1),
    // xs=1 -> ch 8cg+4..+7 (A2,A3)
    float2 f0 = __half22float2(xs ? A2 : A0);
    float2 f1 = __half22float2(xs ? A3 : A1);
    float4 r = make_float4(f0.x, f0.y, f1.x, f1.y);
    __stcs(reinterpret_cast<float4*>(out) + q * 4 + (cg * 2 + xs), r);
}

// ---------------------------------------------------------------------------
extern "C" void kernel_launch(void* const* d_in, const int* in_sizes, int n_in,
                              void* d_out, int out_size) {
    const float* uv  = (const float*)d_in[0];
    const float* p   = (const float*)d_in[1];
    const float* tex = (const float*)d_in[2];
    float* out = (float*)d_out;
    int N = in_sizes[1];          // number of queries (p element count)

    // 1024 transpose blocks + ceil(174752/256)=683 mips blocks
    k_prep<<<1707, 256>>>(tex);
    int total = N * 4;
    k_sample<<<(total + 255) / 256, 256>>>(uv, p, out, N);
}

// round 14
// speedup vs baseline: 1.0689x; 1.0689x over previous
#include <cuda_runtime.h>
#include <cuda_fp16.h>

// ---------------------------------------------------------------------------
// Mipmapped texture sampling, GB300 — fp16 HYBRID pyramid.
//   Level 0: single-width HWC (32B/texel) — the x0/x1 span is contiguous
//            64B anyway; only 1/7 of queries touch level 0, so straddles
//            there are statistically negligible and we keep the fast
//            transpose and the small 8MB footprint.
//   Levels 1-7: DOUBLED-PAIR blocks [texel x | texel min(x+1,s-1)] = 64B
//            aligned -> exactly one L1 line touch per (level,row) span.
// Both layouts expose the same lane-chunk order [x0.lo|x0.hi|x1.lo|x1.hi],
// so sample differs only in one address formula.
// Level i (i>=1) texel = 0.25 * 2x2 of base pixels at y0 = y*2^i + 2^(i-1)-1
// (exact algebra of align_corners=False downsample by 2^i): mips read the
// fp32 input directly, fused with the transpose in one launch.
// Sample: 4 lanes/query; lanes xs=0 compute level-l0 setup, xs=1 compute l1,
// exchanged via width-4 shuffles. y1 row unclamped (weight exactly 0 when it
// would clamp); overrun lands in the next level / zero pad.
// ---------------------------------------------------------------------------

#define NLEV 8

// uint4 units: level0 single = 524288; doubled L1..L7 = 349504; pad 16
// halves: (524288 + 349504 + 16) * 8 = 6,990,464
__device__ __align__(16) __half g_pyr[6990464];

// level base offsets in uint4 (16B) units (level 0 single, 1..7 doubled)
__constant__ int coff4[NLEV] = {
    0, 524288, 786432, 851968, 868352, 872448, 873472, 873728
};

__device__ __forceinline__ unsigned f2u(float a, float b) {
    __half2 h = __floats2half2_rn(a, b);
    return *reinterpret_cast<const unsigned*>(&h);
}
__device__ __forceinline__ __half2 u2h(unsigned u) {
    return *reinterpret_cast<const __half2*>(&u);
}
__device__ __forceinline__ unsigned h2u(__half2 h) {
    return *reinterpret_cast<const unsigned*>(&h);
}
__device__ __forceinline__ float f2get(const float2& v, int j) {
    return j == 0 ? v.x : v.y;
}

// ---------------------------------------------------------------------------
// Fused prep kernel.
// Blocks [0,1024):    transpose (identical to the fast R12 path).
//   thread = (pixel-pair, channel-half): 8 x LDG.64 plane loads, 2 x STG.128
//   into single-width level 0.
// Blocks [1024,1707): mips. thread = (texel, channel-half): 2x2 fp32 average
//   of the base, written into the doubled blocks: blk(x).chunk(t),
//   blk(x-1).chunk(2+t) (if x>0), blk(s-1).chunk(2+t) (edge clamp).
// ---------------------------------------------------------------------------
__global__ void k_prep(const float* __restrict__ tex) {
    const int plane = 512 * 512;
    uint4* pyr4 = reinterpret_cast<uint4*>(g_pyr);
    if (blockIdx.x < 1024) {
        int idx = blockIdx.x * blockDim.x + threadIdx.x;   // < 262144
        int t   = idx & 1;        // 0: channels 0-7, 1: channels 8-15
        int grp = idx >> 1;       // pixel pair index
        const int plane2 = plane / 2;
        const float2* src = reinterpret_cast<const float2*>(tex) + (8 * t) * plane2 + grp;

        float2 v0 = __ldg(src);
        float2 v1 = __ldg(src + plane2);
        float2 v2 = __ldg(src + 2 * plane2);
        float2 v3 = __ldg(src + 3 * plane2);
        float2 v4 = __ldg(src + 4 * plane2);
        float2 v5 = __ldg(src + 5 * plane2);
        float2 v6 = __ldg(src + 6 * plane2);
        float2 v7 = __ldg(src + 7 * plane2);

#pragma unroll
        for (int j = 0; j < 2; j++) {
            uint4 a;
            a.x = f2u(f2get(v0, j), f2get(v1, j));
            a.y = f2u(f2get(v2, j), f2get(v3, j));
            a.z = f2u(f2get(v4, j), f2get(v5, j));
            a.w = f2u(f2get(v6, j), f2get(v7, j));
            pyr4[(2 * grp + j) * 2 + t] = a;
        }
    } else {
        int idx = (blockIdx.x - 1024) * blockDim.x + threadIdx.x;
        if (idx >= 2 * 87376) return;
        int t   = idx & 1;
        int rem = idx >> 1;

        int l = 1;
#pragma unroll
        for (int i = 1; i < NLEV; i++) {
            int np = (512 >> i) * (512 >> i);
            if (rem < np) { l = i; break; }
            rem -= np;
        }
        int s  = 512 >> l;
        int x  = rem & (s - 1);
        int y  = rem >> (9 - l);
        int sc = 1 << l;
        int x0 = x * sc + (sc >> 1) - 1;
        int y0 = y * sc + (sc >> 1) - 1;

        const float* src = tex + (8 * t) * plane + y0 * 512 + x0;
#define AVG(c) (0.25f * (__ldg(src + (c) * plane)       + __ldg(src + (c) * plane + 1) + \
                         __ldg(src + (c) * plane + 512) + __ldg(src + (c) * plane + 513)))
        float a0 = AVG(0), a1 = AVG(1), a2 = AVG(2), a3 = AVG(3);
        float a4 = AVG(4), a5 = AVG(5), a6 = AVG(6), a7 = AVG(7);
#undef AVG
        uint4 r;
        r.x = f2u(a0, a1);
        r.y = f2u(a2, a3);
        r.z = f2u(a4, a5);
        r.w = f2u(a6, a7);

        int blkbase = coff4[l] + (y * s + x) * 4;
        pyr4[blkbase + t] = r;                          // blk(x).chunk(t)
        if (x > 0)      pyr4[blkbase - 2 + t] = r;      // blk(x-1).chunk(2+t)
        if (x == s - 1) pyr4[blkbase + 2 + t] = r;      // edge clamp duplicate
    }
}

// ---------------------------------------------------------------------------
// Sample kernel. 4 threads/query: t = 2*xs + cg.
// Lanes xs=0 compute level-l0 setup, xs=1 compute level-l1 setup; the
// (idx, rowstride, fx, fy) tuples are exchanged with width-4 shuffles.
// Lane t loads chunk t of the 64B span [x0.lo|x0.hi|x1.lo|x1.hi] for both
// rows of both levels: 4 x LDG.128 per thread, straddle-free on levels>=1.
// Accumulation in half2 (HMUL2/HFMA2), xor-2 lane reduction, float4 store.
// ---------------------------------------------------------------------------
__global__ void k_sample(const float* __restrict__ uv,
                         const float* __restrict__ p,
                         float* __restrict__ out, int N) {
    int idx = blockIdx.x * blockDim.x + threadIdx.x;
    int q = idx >> 2;
    if (q >= N) return;
    int t  = idx & 3;
    int xs = t >> 1;      // 0: x0 texel / level-A duty, 1: x1 texel / level-B duty
    int cg = t & 1;       // 0: channels 0-7, 1: channels 8-15

    float2 uvq = __ldg(reinterpret_cast<const float2*>(uv) + q);
    float  pp  = __ldg(&p[q]);

    float lf = pp * (float)(NLEV - 1);
    int   l0 = min((int)lf, NLEV - 1);
    float alpha = lf - (float)l0;

    float gx = 2.0f * uvq.x - 1.0f;
    float gy = 2.0f * uvq.y - 1.0f;

    // my level: lanes xs=0 -> l0, lanes xs=1 -> l1
    int myl = min(l0 + xs, NLEV - 1);
    int s   = 512 >> myl;
    float fs = (float)(s - 1);
    float xx = fminf(fmaxf((gx + 1.0f) * 0.5f * fs, 0.0f), fs);
    float yy = fminf(fmaxf((gy + 1.0f) * 0.5f * fs, 0.0f), fs);
    int x0 = (int)xx;           // trunc == floor (xx >= 0)
    int y0 = (int)yy;
    float fx = xx - (float)x0;  // 0 exactly when x1/y1 would clamp
    float fy = yy - (float)y0;
    // level 0: single layout (texel = 2 uint4, span contiguous);
    // levels >= 1: doubled blocks (4 uint4 per block)
    int myidx, myrs;
    if (myl == 0) {
        myidx = (y0 << 10) + x0 * 2;      // (y0*512 + x0) * 2
        myrs  = 1024;
    } else {
        myidx = coff4[myl] + (y0 * s + x0) * 4;
        myrs  = 4 * s;
    }

    // exchange level setups within the 4-lane group
    unsigned m = __activemask();
    int   idxA = __shfl_sync(m, myidx, 0, 4);
    int   rsA  = __shfl_sync(m, myrs,  0, 4);
    float fxA  = __shfl_sync(m, fx,    0, 4);
    float fyA  = __shfl_sync(m, fy,    0, 4);
    int   idxB = __shfl_sync(m, myidx, 2, 4);
    int   rsB  = __shfl_sync(m, myrs,  2, 4);
    float fxB  = __shfl_sync(m, fx,    2, 4);
    float fyB  = __shfl_sync(m, fy,    2, 4);

    const uint4* pyr4 = reinterpret_cast<const uint4*>(g_pyr);
    // batch all 4 span loads (both levels, both rows); y1 unclamped (weight 0)
    uint4 va0 = __ldg(pyr4 + idxA + t);
    uint4 va1 = __ldg(pyr4 + idxA + rsA + t);
    uint4 vb0 = __ldg(pyr4 + idxB + t);
    uint4 vb1 = __ldg(pyr4 + idxB + rsB + t);

    float wxa = xs ? fxA : (1.0f - fxA);
    float wxb = xs ? fxB : (1.0f - fxB);
    float la  = (1.0f - alpha) * wxa;
    float lb  = alpha * wxb;
    __half2 hw0 = __float2half2_rn(la * (1.0f - fyA));
    __half2 hw1 = __float2half2_rn(la * fyA);
    __half2 hw2 = __float2half2_rn(lb * (1.0f - fyB));
    __half2 hw3 = __float2half2_rn(lb * fyB);

    // half2 accumulation: 4 HMUL2 + 12 HFMA2
    __half2 A0 = __hmul2(u2h(va0.x), hw0);
    __half2 A1 = __hmul2(u2h(va0.y), hw0);
    __half2 A2 = __hmul2(u2h(va0.z), hw0);
    __half2 A3 = __hmul2(u2h(va0.w), hw0);
    A0 = __hfma2(u2h(va1.x), hw1, A0);
    A1 = __hfma2(u2h(va1.y), hw1, A1);
    A2 = __hfma2(u2h(va1.z), hw1, A2);
    A3 = __hfma2(u2h(va1.w), hw1, A3);
    A0 = __hfma2(u2h(vb0.x), hw2, A0);
    A1 = __hfma2(u2h(vb0.y), hw2, A1);
    A2 = __hfma2(u2h(vb0.z), hw2, A2);
    A3 = __hfma2(u2h(vb0.w), hw2, A3);
    A0 = __hfma2(u2h(vb1.x), hw3, A0);
    A1 = __hfma2(u2h(vb1.y), hw3, A1);
    A2 = __hfma2(u2h(vb1.z), hw3, A2);
    A3 = __hfma2(u2h(vb1.w), hw3, A3);

    // combine x0-side and x1-side partial sums (lane ^ 2)
    A0 = __hadd2(A0, u2h(__shfl_xor_sync(m, h2u(A0), 2)));
    A1 = __hadd2(A1, u2h(__shfl_xor_sync(m, h2u(A1), 2)));
    A2 = __hadd2(A2, u2h(__shfl_xor_sync(m, h2u(A2), 2)));
    A3 = __hadd2(A3, u2h(__shfl_xor_sync(m, h2u(A3), 2)));

    // lane (xs,cg) stores float4 slot cg*2+xs: xs=0 -> ch 8cg..+3 (A0,A1),
    // xs=1 -> ch 8cg+4..+7 (A2,A3)
    float2 f0 = __half22float2(xs ? A2 : A0);
    float2 f1 = __half22float2(xs ? A3 : A1);
    float4 r = make_float4(f0.x, f0.y, f1.x, f1.y);
    __stcs(reinterpret_cast<float4*>(out) + q * 4 + (cg * 2 + xs), r);
}

// ---------------------------------------------------------------------------
extern "C" void kernel_launch(void* const* d_in, const int* in_sizes, int n_in,
                              void* d_out, int out_size) {
    const float* uv  = (const float*)d_in[0];
    const float* p   = (const float*)d_in[1];
    const float* tex = (const float*)d_in[2];
    float* out = (float*)d_out;
    int N = in_sizes[1];          // number of queries (p element count)

    // 1024 transpose blocks + ceil(174752/256)=683 mips blocks
    k_prep<<<1707, 256>>>(tex);
    int total = N * 4;
    k_sample<<<(total + 255) / 256, 256>>>(uv, p, out, N);
}

// round 15
// speedup vs baseline: 1.0996x; 1.0287x over previous
#include <cuda_runtime.h>
#include <cuda_fp16.h>

// ---------------------------------------------------------------------------
// Mipmapped texture sampling, GB300 — fp16 pyramid (32B/texel, HWC), R12
// layout (best measured sample: 28.3us) + smem-staged transpose in prep.
// Level i (i>=1) texel = 0.25 * 2x2 of base pixels at y0 = y*2^i + 2^(i-1)-1
// (exact algebra of align_corners=False downsample by 2^i): mips read the
// fp32 input directly; transpose and mips fused in one launch.
// Sample: 4 lanes/query fetch the contiguous 64B x0/x1 span of each
// (level,row) with ONE warp-LDG; half2 accumulation; xor-2 reduction.
// x1/y1 unclamped (bilinear weight exactly 0 when clamping would apply);
// zero pad after level 7 covers the only true overrun.
// ---------------------------------------------------------------------------

#define NLEV 8

// 5,592,320 pyramid halves + 128 zero-pad halves for weight-0 edge overreads
__device__ __align__(16) __half g_pyr[5592448];

__constant__ int c_off[NLEV] = {
    0, 4194304, 5242880, 5505024, 5570560, 5586944, 5591040, 5592064
};

__device__ __forceinline__ unsigned f2u(float a, float b) {
    __half2 h = __floats2half2_rn(a, b);
    return *reinterpret_cast<const unsigned*>(&h);
}
__device__ __forceinline__ __half2 u2h(unsigned u) {
    return *reinterpret_cast<const __half2*>(&u);
}
__device__ __forceinline__ unsigned h2u(__half2 h) {
    return *reinterpret_cast<const unsigned*>(&h);
}

// ---------------------------------------------------------------------------
// Fused prep kernel.
// Blocks [0,2048): smem-staged transpose. Tile = 128 consecutive pixels.
//   Load: warp w owns channels (2w, 2w+1): lane l does 2 x LDG.128 (pixels
//   4l..4l+3 of each plane), packs 4 half2 (ch-pair per pixel), 1 STS.128.
//   Smem stride 132 words (132 % 32 == 4) -> read phase is bank-conflict
//   free (addr ≡ 4*c2 + 16*W + (i>>1) covers all 32 banks).
//   Write: thread (p = tid>>1, h = tid&1): 4 x LDS.32 (channel pairs
//   4h..4h+3 at pixel p) -> STG.128 at uint4 index 2*P + tid (sequential).
// Blocks [2048,2731): mips. thread = (texel, channel-half): 2x2 fp32
//   average of base pixels, one STG.128 into level l.
// ---------------------------------------------------------------------------
__global__ void k_prep(const float* __restrict__ tex) {
    const int plane = 512 * 512;
    uint4* pyr4 = reinterpret_cast<uint4*>(g_pyr);
    __shared__ unsigned sm[8][132];

    if (blockIdx.x < 2048) {
        int w = threadIdx.x >> 5;          // warp: channel pair (2w, 2w+1)
        int l = threadIdx.x & 31;
        int P = blockIdx.x * 128;          // tile base pixel

        const float4* s0 = reinterpret_cast<const float4*>(tex + (2 * w) * plane) + (P >> 2) + l;
        const float4* s1 = reinterpret_cast<const float4*>(tex + (2 * w + 1) * plane) + (P >> 2) + l;
        float4 a = __ldg(s0);
        float4 b = __ldg(s1);

        uint4 st;
        st.x = f2u(a.x, b.x);
        st.y = f2u(a.y, b.y);
        st.z = f2u(a.z, b.z);
        st.w = f2u(a.w, b.w);
        *reinterpret_cast<uint4*>(&sm[w][4 * l]) = st;
        __syncthreads();

        int p = threadIdx.x >> 1;          // pixel within tile
        int h = threadIdx.x & 1;           // chunk (channels 8h..8h+7)
        uint4 o;
        o.x = sm[4 * h + 0][p];
        o.y = sm[4 * h + 1][p];
        o.z = sm[4 * h + 2][p];
        o.w = sm[4 * h + 3][p];
        pyr4[2 * P + threadIdx.x] = o;     // = (P+p)*2 + h, fully sequential
    } else {
        int idx = (blockIdx.x - 2048) * blockDim.x + threadIdx.x;
        if (idx >= 2 * 87376) return;
        int t   = idx & 1;
        int rem = idx >> 1;

        int l = 1;
#pragma unroll
        for (int i = 1; i < NLEV; i++) {
            int np = (512 >> i) * (512 >> i);
            if (rem < np) { l = i; break; }
            rem -= np;
        }
        int s  = 512 >> l;
        int x  = rem & (s - 1);
        int y  = rem >> (9 - l);
        int sc = 1 << l;
        int x0 = x * sc + (sc >> 1) - 1;
        int y0 = y * sc + (sc >> 1) - 1;

        const float* src = tex + (8 * t) * plane + y0 * 512 + x0;
#define AVG(c) (0.25f * (__ldg(src + (c) * plane)       + __ldg(src + (c) * plane + 1) + \
                         __ldg(src + (c) * plane + 512) + __ldg(src + (c) * plane + 513)))
        float a0 = AVG(0), a1 = AVG(1), a2 = AVG(2), a3 = AVG(3);
        float a4 = AVG(4), a5 = AVG(5), a6 = AVG(6), a7 = AVG(7);
#undef AVG
        uint4 r;
        r.x = f2u(a0, a1);
        r.y = f2u(a2, a3);
        r.z = f2u(a4, a5);
        r.w = f2u(a6, a7);
        reinterpret_cast<uint4*>(g_pyr + c_off[l])[(y * s + x) * 2 + t] = r;
    }
}

// ---------------------------------------------------------------------------
// Sample kernel (identical to R12 / best measured). 4 threads/query:
// xs = t>>1 (x0 vs x1 texel), cg = t&1 (channels 0-7 vs 8-15). Lane t loads
// bytes [16t,16t+16) of the 64B span [texel x0 | texel x1] for 4 (level,row)
// pairs -> 4 LDG.128 per thread. Accumulation in half2.
// ---------------------------------------------------------------------------
__device__ __forceinline__ void lvl_addr(int l, float gx, float gy, int t,
        const uint4*& r0, const uint4*& r1, float& fx, float& fy) {
    int   s  = 512 >> l;
    float fs = (float)(s - 1);
    float x = fminf(fmaxf((gx + 1.0f) * 0.5f * fs, 0.0f), fs);
    float y = fminf(fmaxf((gy + 1.0f) * 0.5f * fs, 0.0f), fs);
    int x0 = (int)x;             // trunc == floor (x >= 0)
    int y0 = (int)y;
    fx = x - (float)x0;          // 0 exactly when x1/y1 would clamp
    fy = y - (float)y0;
    const uint4* b = reinterpret_cast<const uint4*>(g_pyr + c_off[l]);
    r0 = b + (y0 * s + x0) * 2 + t;   // lane t: 16B chunk of the 64B x0|x1 span
    r1 = r0 + 2 * s;                  // row y0+1 (unclamped; weight 0 at edge)
}

__global__ void k_sample(const float* __restrict__ uv,
                         const float* __restrict__ p,
                         float* __restrict__ out, int N) {
    int idx = blockIdx.x * blockDim.x + threadIdx.x;
    int q = idx >> 2;
    if (q >= N) return;
    int t  = idx & 3;
    int xs = t >> 1;      // 0: x0 texel, 1: x1 texel
    int cg = t & 1;       // 0: channels 0-7, 1: channels 8-15

    float2 uvq = __ldg(reinterpret_cast<const float2*>(uv) + q);
    float  pp  = __ldg(&p[q]);

    float lf = pp * (float)(NLEV - 1);
    int   l0 = min((int)lf, NLEV - 1);
    int   l1 = min(l0 + 1, NLEV - 1);
    float alpha = lf - (float)l0;

    float gx = 2.0f * uvq.x - 1.0f;
    float gy = 2.0f * uvq.y - 1.0f;

    const uint4 *a0, *a1, *b0, *b1;
    float fxa, fya, fxb, fyb;
    lvl_addr(l0, gx, gy, t, a0, a1, fxa, fya);
    lvl_addr(l1, gx, gy, t, b0, b1, fxb, fyb);

    // batch all 4 span loads (both levels, both rows)
    uint4 va0 = __ldg(a0);
    uint4 va1 = __ldg(a1);
    uint4 vb0 = __ldg(b0);
    uint4 vb1 = __ldg(b1);

    float wxa = xs ? fxa : (1.0f - fxa);
    float wxb = xs ? fxb : (1.0f - fxb);
    float la  = (1.0f - alpha) * wxa;
    float lb  = alpha * wxb;
    __half2 hw0 = __float2half2_rn(la * (1.0f - fya));
    __half2 hw1 = __float2half2_rn(la * fya);
    __half2 hw2 = __float2half2_rn(lb * (1.0f - fyb));
    __half2 hw3 = __float2half2_rn(lb * fyb);

    // half2 accumulation: 4 HMUL2 + 12 HFMA2, no per-texel converts
    __half2 A0 = __hmul2(u2h(va0.x), hw0);
    __half2 A1 = __hmul2(u2h(va0.y), hw0);
    __half2 A2 = __hmul2(u2h(va0.z), hw0);
    __half2 A3 = __hmul2(u2h(va0.w), hw0);
    A0 = __hfma2(u2h(va1.x), hw1, A0);
    A1 = __hfma2(u2h(va1.y), hw1, A1);
    A2 = __hfma2(u2h(va1.z), hw1, A2);
    A3 = __hfma2(u2h(va1.w), hw1, A3);
    A0 = __hfma2(u2h(vb0.x), hw2, A0);
    A1 = __hfma2(u2h(vb0.y), hw2, A1);
    A2 = __hfma2(u2h(vb0.z), hw2, A2);
    A3 = __hfma2(u2h(vb0.w), hw2, A3);
    A0 = __hfma2(u2h(vb1.x), hw3, A0);
    A1 = __hfma2(u2h(vb1.y), hw3, A1);
    A2 = __hfma2(u2h(vb1.z), hw3, A2);
    A3 = __hfma2(u2h(vb1.w), hw3, A3);

    // combine x0-side and x1-side partial sums (lane ^ 2)
    const unsigned FULL = 0xFFFFFFFFu;
    A0 = __hadd2(A0, u2h(__shfl_xor_sync(FULL, h2u(A0), 2)));
    A1 = __hadd2(A1, u2h(__shfl_xor_sync(FULL, h2u(A1), 2)));
    A2 = __hadd2(A2, u2h(__shfl_xor_sync(FULL, h2u(A2), 2)));
    A3 = __hadd2(A3, u2h(__shfl_xor_sync(FULL, h2u(A3), 2)));

    // lane (xs,cg) stores float4 slot cg*2+xs: xs=0 -> ch 8cg..+3 (A0,A1),
    // xs=1 -> ch 8cg+4..+7 (A2,A3)
    float2 f0 = __half22float2(xs ? A2 : A0);
    float2 f1 = __half22float2(xs ? A3 : A1);
    float4 r = make_float4(f0.x, f0.y, f1.x, f1.y);
    __stcs(reinterpret_cast<float4*>(out) + q * 4 + (cg * 2 + xs), r);
}

// ---------------------------------------------------------------------------
extern "C" void kernel_launch(void* const* d_in, const int* in_sizes, int n_in,
                              void* d_out, int out_size) {
    const float* uv  = (const float*)d_in[0];
    const float* p   = (const float*)d_in[1];
    const float* tex = (const float*)d_in[2];
    float* out = (float*)d_out;
    int N = in_sizes[1];          // number of queries (p element count)

    // 2048 transpose tiles + ceil(174752/256)=683 mips blocks
    k_prep<<<2731, 256>>>(tex);
    int total = N * 4;
    k_sample<<<(total + 255) / 256, 256>>>(uv, p, out, N);
}

// round 16
// speedup vs baseline: 1.1099x; 1.0094x over previous
#include <cuda_runtime.h>
#include <cuda_fp16.h>

// ---------------------------------------------------------------------------
// Mipmapped texture sampling, GB300 — fp16 pyramid (32B/texel, HWC).
// Level i (i>=1) texel = 0.25 * 2x2 of base pixels at y0 = y*2^i + 2^(i-1)-1
// (exact algebra of align_corners=False downsample by 2^i).
// Level 1's window (x0=2x, y0=2y) is block-aligned, so level 1 is computed
// INSIDE the transpose from the already-loaded fp32 pixels; the mips tail
// only builds levels 2-7 (5.6MB of reads instead of 22MB).
// Sample: 4 lanes/query fetch the contiguous 64B x0/x1 span of each
// (level,row) with ONE warp-LDG; half2 accumulation; xor-2 reduction.
// x1/y1 unclamped (bilinear weight exactly 0 when clamping would apply);
// zero pad after level 7 covers the only true overrun.
// ---------------------------------------------------------------------------

#define NLEV 8

// 5,592,320 pyramid halves + 128 zero-pad halves for weight-0 edge overreads
__device__ __align__(16) __half g_pyr[5592448];

__constant__ int c_off[NLEV] = {
    0, 4194304, 5242880, 5505024, 5570560, 5586944, 5591040, 5592064
};

__device__ __forceinline__ unsigned f2u(float a, float b) {
    __half2 h = __floats2half2_rn(a, b);
    return *reinterpret_cast<const unsigned*>(&h);
}
__device__ __forceinline__ __half2 u2h(unsigned u) {
    return *reinterpret_cast<const __half2*>(&u);
}
__device__ __forceinline__ unsigned h2u(__half2 h) {
    return *reinterpret_cast<const unsigned*>(&h);
}

// ---------------------------------------------------------------------------
// Fused prep kernel.
// Blocks [0,1024): transpose + level 1. Thread = (channel-quartet t, 2x2
//   pixel block (bx,by)): 8 x LDG.64 (4 planes x 2 rows, proven R9 shape),
//   writes 4 level-0 texel chunks (uint2 each) + 1 level-1 chunk computed
//   from the same fp32 values.
// Blocks [1024,1195): mips levels 2-7. thread = (texel, channel-half):
//   2x2 fp32 average of base pixels, one STG.128 into level l.
// ---------------------------------------------------------------------------
__global__ void k_prep(const float* __restrict__ tex) {
    const int plane  = 512 * 512;
    const int plane2 = plane / 2;
    if (blockIdx.x < 1024) {
        int idx = blockIdx.x * blockDim.x + threadIdx.x;   // < 262144
        int t  = idx & 3;          // channel quartet 4t..4t+3
        int b  = idx >> 2;
        int bx = b & 255;          // 2x2 block coords
        int by = b >> 8;

        const float2* s0 = reinterpret_cast<const float2*>(tex)
                         + (4 * t) * plane2 + (2 * by) * 256 + bx;
        // rows 2by (r0) and 2by+1 (r1) of 4 consecutive planes
        float2 r0c0 = __ldg(s0);
        float2 r1c0 = __ldg(s0 + 256);
        float2 r0c1 = __ldg(s0 + plane2);
        float2 r1c1 = __ldg(s0 + plane2 + 256);
        float2 r0c2 = __ldg(s0 + 2 * plane2);
        float2 r1c2 = __ldg(s0 + 2 * plane2 + 256);
        float2 r0c3 = __ldg(s0 + 3 * plane2);
        float2 r1c3 = __ldg(s0 + 3 * plane2 + 256);

        uint2* pyr2 = reinterpret_cast<uint2*>(g_pyr);
        int p00 = (2 * by) * 512 + 2 * bx;       // pixel (2bx, 2by)
        uint2 w;
        // level 0, pixel (2bx, 2by)
        w.x = f2u(r0c0.x, r0c1.x); w.y = f2u(r0c2.x, r0c3.x);
        pyr2[p00 * 4 + t] = w;
        // pixel (2bx+1, 2by)
        w.x = f2u(r0c0.y, r0c1.y); w.y = f2u(r0c2.y, r0c3.y);
        pyr2[(p00 + 1) * 4 + t] = w;
        // pixel (2bx, 2by+1)
        w.x = f2u(r1c0.x, r1c1.x); w.y = f2u(r1c2.x, r1c3.x);
        pyr2[(p00 + 512) * 4 + t] = w;
        // pixel (2bx+1, 2by+1)
        w.x = f2u(r1c0.y, r1c1.y); w.y = f2u(r1c2.y, r1c3.y);
        pyr2[(p00 + 513) * 4 + t] = w;

        // level 1 texel (bx, by): 0.25 * sum of the 2x2 fp32 block
        float m0 = 0.25f * (r0c0.x + r0c0.y + r1c0.x + r1c0.y);
        float m1 = 0.25f * (r0c1.x + r0c1.y + r1c1.x + r1c1.y);
        float m2 = 0.25f * (r0c2.x + r0c2.y + r1c2.x + r1c2.y);
        float m3 = 0.25f * (r0c3.x + r0c3.y + r1c3.x + r1c3.y);
        w.x = f2u(m0, m1); w.y = f2u(m2, m3);
        pyr2[1048576 + (by * 256 + bx) * 4 + t] = w;   // c_off[1]/4 = 1048576
    } else {
        int idx = (blockIdx.x - 1024) * blockDim.x + threadIdx.x;
        if (idx >= 2 * 21840) return;          // levels 2..7: 21840 texels
        int t   = idx & 1;
        int rem = idx >> 1;

        int l = 2;
#pragma unroll
        for (int i = 2; i < NLEV; i++) {
            int np = (512 >> i) * (512 >> i);
            if (rem < np) { l = i; break; }
            rem -= np;
        }
        int s  = 512 >> l;
        int x  = rem & (s - 1);
        int y  = rem >> (9 - l);
        int sc = 1 << l;
        int x0 = x * sc + (sc >> 1) - 1;
        int y0 = y * sc + (sc >> 1) - 1;

        const float* src = tex + (8 * t) * plane + y0 * 512 + x0;
#define AVG(c) (0.25f * (__ldg(src + (c) * plane)       + __ldg(src + (c) * plane + 1) + \
                         __ldg(src + (c) * plane + 512) + __ldg(src + (c) * plane + 513)))
        float a0 = AVG(0), a1 = AVG(1), a2 = AVG(2), a3 = AVG(3);
        float a4 = AVG(4), a5 = AVG(5), a6 = AVG(6), a7 = AVG(7);
#undef AVG
        uint4 r;
        r.x = f2u(a0, a1);
        r.y = f2u(a2, a3);
        r.z = f2u(a4, a5);
        r.w = f2u(a6, a7);
        reinterpret_cast<uint4*>(g_pyr + c_off[l])[(y * s + x) * 2 + t] = r;
    }
}

// ---------------------------------------------------------------------------
// Sample kernel (identical to R12/R15 best: 28.3us). 4 threads/query:
// xs = t>>1 (x0 vs x1 texel), cg = t&1 (channels 0-7 vs 8-15). Lane t loads
// bytes [16t,16t+16) of the 64B span [texel x0 | texel x1] for 4 (level,row)
// pairs -> 4 LDG.128 per thread. Accumulation in half2.
// ---------------------------------------------------------------------------
__device__ __forceinline__ void lvl_addr(int l, float gx, float gy, int t,
        const uint4*& r0, const uint4*& r1, float& fx, float& fy) {
    int   s  = 512 >> l;
    float fs = (float)(s - 1);
    float x = fminf(fmaxf((gx + 1.0f) * 0.5f * fs, 0.0f), fs);
    float y = fminf(fmaxf((gy + 1.0f) * 0.5f * fs, 0.0f), fs);
    int x0 = (int)x;             // trunc == floor (x >= 0)
    int y0 = (int)y;
    fx = x - (float)x0;          // 0 exactly when x1/y1 would clamp
    fy = y - (float)y0;
    const uint4* b = reinterpret_cast<const uint4*>(g_pyr + c_off[l]);
    r0 = b + (y0 * s + x0) * 2 + t;   // lane t: 16B chunk of the 64B x0|x1 span
    r1 = r0 + 2 * s;                  // row y0+1 (unclamped; weight 0 at edge)
}

__global__ void k_sample(const float* __restrict__ uv,
                         const float* __restrict__ p,
                         float* __restrict__ out, int N) {
    int idx = blockIdx.x * blockDim.x + threadIdx.x;
    int q = idx >> 2;
    if (q >= N) return;
    int t  = idx & 3;
    int xs = t >> 1;      // 0: x0 texel, 1: x1 texel
    int cg = t & 1;       // 0: channels 0-7, 1: channels 8-15

    float2 uvq = __ldg(reinterpret_cast<const float2*>(uv) + q);
    float  pp  = __ldg(&p[q]);

    float lf = pp * (float)(NLEV - 1);
    int   l0 = min((int)lf, NLEV - 1);
    int   l1 = min(l0 + 1, NLEV - 1);
    float alpha = lf - (float)l0;

    float gx = 2.0f * uvq.x - 1.0f;
    float gy = 2.0f * uvq.y - 1.0f;

    const uint4 *a0, *a1, *b0, *b1;
    float fxa, fya, fxb, fyb;
    lvl_addr(l0, gx, gy, t, a0, a1, fxa, fya);
    lvl_addr(l1, gx, gy, t, b0, b1, fxb, fyb);

    // batch all 4 span loads (both levels, both rows)
    uint4 va0 = __ldg(a0);
    uint4 va1 = __ldg(a1);
    uint4 vb0 = __ldg(b0);
    uint4 vb1 = __ldg(b1);

    float wxa = xs ? fxa : (1.0f - fxa);
    float wxb = xs ? fxb : (1.0f - fxb);
    float la  = (1.0f - alpha) * wxa;
    float lb  = alpha * wxb;
    __half2 hw0 = __float2half2_rn(la * (1.0f - fya));
    __half2 hw1 = __float2half2_rn(la * fya);
    __half2 hw2 = __float2half2_rn(lb * (1.0f - fyb));
    __half2 hw3 = __float2half2_rn(lb * fyb);

    // half2 accumulation: 4 HMUL2 + 12 HFMA2, no per-texel converts
    __half2 A0 = __hmul2(u2h(va0.x), hw0);
    __half2 A1 = __hmul2(u2h(va0.y), hw0);
    __half2 A2 = __hmul2(u2h(va0.z), hw0);
    __half2 A3 = __hmul2(u2h(va0.w), hw0);
    A0 = __hfma2(u2h(va1.x), hw1, A0);
    A1 = __hfma2(u2h(va1.y), hw1, A1);
    A2 = __hfma2(u2h(va1.z), hw1, A2);
    A3 = __hfma2(u2h(va1.w), hw1, A3);
    A0 = __hfma2(u2h(vb0.x), hw2, A0);
    A1 = __hfma2(u2h(vb0.y), hw2, A1);
    A2 = __hfma2(u2h(vb0.z), hw2, A2);
    A3 = __hfma2(u2h(vb0.w), hw2, A3);
    A0 = __hfma2(u2h(vb1.x), hw3, A0);
    A1 = __hfma2(u2h(vb1.y), hw3, A1);
    A2 = __hfma2(u2h(vb1.z), hw3, A2);
    A3 = __hfma2(u2h(vb1.w), hw3, A3);

    // combine x0-side and x1-side partial sums (lane ^ 2)
    const unsigned FULL = 0xFFFFFFFFu;
    A0 = __hadd2(A0, u2h(__shfl_xor_sync(FULL, h2u(A0), 2)));
    A1 = __hadd2(A1, u2h(__shfl_xor_sync(FULL, h2u(A1), 2)));
    A2 = __hadd2(A2, u2h(__shfl_xor_sync(FULL, h2u(A2), 2)));
    A3 = __hadd2(A3, u2h(__shfl_xor_sync(FULL, h2u(A3), 2)));

    // lane (xs,cg) stores float4 slot cg*2+xs: xs=0 -> ch 8cg..+3 (A0,A1),
    // xs=1 -> ch 8cg+4..+7 (A2,A3)
    float2 f0 = __half22float2(xs ? A2 : A0);
    float2 f1 = __half22float2(xs ? A3 : A1);
    float4 r = make_float4(f0.x, f0.y, f1.x, f1.y);
    __stcs(reinterpret_cast<float4*>(out) + q * 4 + (cg * 2 + xs), r);
}

// ---------------------------------------------------------------------------
extern "C" void kernel_launch(void* const* d_in, const int* in_sizes, int n_in,
                              void* d_out, int out_size) {
    const float* uv  = (const float*)d_in[0];
    const float* p   = (const float*)d_in[1];
    const float* tex = (const float*)d_in[2];
    float* out = (float*)d_out;
    int N = in_sizes[1];          // number of queries (p element count)

    // 1024 transpose+L1 blocks + ceil(43680/256)=171 mips blocks
    k_prep<<<1195, 256>>>(tex);
    int total = N * 4;
    k_sample<<<(total + 255) / 256, 256>>>(uv, p, out, N);
}

// round 17
// speedup vs baseline: 1.2421x; 1.1192x over previous
#include <cuda_runtime.h>
#include <cuda_fp16.h>

// ---------------------------------------------------------------------------
// Mipmapped texture sampling, GB300 — fp16 pyramid (32B/texel, HWC).
// Level i (i>=1) texel = 0.25 * 2x2 of base pixels at y0 = y*2^i + 2^(i-1)-1
// (exact algebra of align_corners=False downsample by 2^i).
// Level 1 is computed inside the transpose (its 2x2 window is block-aligned).
// Mips levels 2-7 run as the FIRST blocks of prep (latency-bound gather
// overlapped under the BW-bound transpose) at 4 threads/texel.
// Sample launches with programmatic dependent launch (PDL): uv/p loads and
// all address math run before cudaGridDependencySynchronize(); pyramid
// reads after. Sample body = R12 best (28.3us): 4 lanes/query, one warp-LDG
// per 64B x0/x1 span, half2 accumulation, xor-2 reduction.
// x1/y1 unclamped (bilinear weight exactly 0 when clamping would apply);
// zero pad after level 7 covers the only true overrun.
// ---------------------------------------------------------------------------

#define NLEV 8

// 5,592,320 pyramid halves + 128 zero-pad halves for weight-0 edge overreads
__device__ __align__(16) __half g_pyr[5592448];

__constant__ int c_off[NLEV] = {
    0, 4194304, 5242880, 5505024, 5570560, 5586944, 5591040, 5592064
};

#define MIPS_BLOCKS 342   // ceil(4*21840/256)

__device__ __forceinline__ unsigned f2u(float a, float b) {
    __half2 h = __floats2half2_rn(a, b);
    return *reinterpret_cast<const unsigned*>(&h);
}
__device__ __forceinline__ __half2 u2h(unsigned u) {
    return *reinterpret_cast<const __half2*>(&u);
}
__device__ __forceinline__ unsigned h2u(__half2 h) {
    return *reinterpret_cast<const unsigned*>(&h);
}

// ---------------------------------------------------------------------------
// Fused prep kernel.
// Blocks [0, MIPS_BLOCKS): mips levels 2-7, scheduled FIRST (latency-bound).
//   thread = (texel, channel-quartet): 16 x LDG.32 (4 channels x 2x2 window),
//   4 fp32 averages, one STG.64.
// Blocks [MIPS_BLOCKS, +1024): transpose + level 1. Thread = (channel-
//   quartet t, 2x2 pixel block): 8 x LDG.64 (4 planes x 2 rows), writes
//   4 level-0 chunks + 1 level-1 chunk computed from the same fp32 values.
// ---------------------------------------------------------------------------
__global__ void k_prep(const float* __restrict__ tex) {
    const int plane  = 512 * 512;
    const int plane2 = plane / 2;
    if (blockIdx.x < MIPS_BLOCKS) {
        int idx = blockIdx.x * blockDim.x + threadIdx.x;
        if (idx >= 4 * 21840) return;          // levels 2..7: 21840 texels
        int t   = idx & 3;                     // channel quartet 4t..4t+3
        int rem = idx >> 2;

        int l = 2;
#pragma unroll
        for (int i = 2; i < NLEV; i++) {
            int np = (512 >> i) * (512 >> i);
            if (rem < np) { l = i; break; }
            rem -= np;
        }
        int s  = 512 >> l;
        int x  = rem & (s - 1);
        int y  = rem >> (9 - l);
        int sc = 1 << l;
        int x0 = x * sc + (sc >> 1) - 1;
        int y0 = y * sc + (sc >> 1) - 1;

        const float* src = tex + (4 * t) * plane + y0 * 512 + x0;
#define AVG(c) (0.25f * (__ldg(src + (c) * plane)       + __ldg(src + (c) * plane + 1) + \
                         __ldg(src + (c) * plane + 512) + __ldg(src + (c) * plane + 513)))
        float a0 = AVG(0), a1 = AVG(1), a2 = AVG(2), a3 = AVG(3);
#undef AVG
        uint2 r;
        r.x = f2u(a0, a1);
        r.y = f2u(a2, a3);
        reinterpret_cast<uint2*>(g_pyr + c_off[l])[(y * s + x) * 4 + t] = r;
    } else {
        int idx = (blockIdx.x - MIPS_BLOCKS) * blockDim.x + threadIdx.x; // < 262144
        int t  = idx & 3;          // channel quartet 4t..4t+3
        int b  = idx >> 2;
        int bx = b & 255;          // 2x2 block coords
        int by = b >> 8;

        const float2* s0 = reinterpret_cast<const float2*>(tex)
                         + (4 * t) * plane2 + (2 * by) * 256 + bx;
        // rows 2by (r0) and 2by+1 (r1) of 4 consecutive planes
        float2 r0c0 = __ldg(s0);
        float2 r1c0 = __ldg(s0 + 256);
        float2 r0c1 = __ldg(s0 + plane2);
        float2 r1c1 = __ldg(s0 + plane2 + 256);
        float2 r0c2 = __ldg(s0 + 2 * plane2);
        float2 r1c2 = __ldg(s0 + 2 * plane2 + 256);
        float2 r0c3 = __ldg(s0 + 3 * plane2);
        float2 r1c3 = __ldg(s0 + 3 * plane2 + 256);

        uint2* pyr2 = reinterpret_cast<uint2*>(g_pyr);
        int p00 = (2 * by) * 512 + 2 * bx;       // pixel (2bx, 2by)
        uint2 w;
        // level 0, pixel (2bx, 2by)
        w.x = f2u(r0c0.x, r0c1.x); w.y = f2u(r0c2.x, r0c3.x);
        pyr2[p00 * 4 + t] = w;
        // pixel (2bx+1, 2by)
        w.x = f2u(r0c0.y, r0c1.y); w.y = f2u(r0c2.y, r0c3.y);
        pyr2[(p00 + 1) * 4 + t] = w;
        // pixel (2bx, 2by+1)
        w.x = f2u(r1c0.x, r1c1.x); w.y = f2u(r1c2.x, r1c3.x);
        pyr2[(p00 + 512) * 4 + t] = w;
        // pixel (2bx+1, 2by+1)
        w.x = f2u(r1c0.y, r1c1.y); w.y = f2u(r1c2.y, r1c3.y);
        pyr2[(p00 + 513) * 4 + t] = w;

        // level 1 texel (bx, by): 0.25 * sum of the 2x2 fp32 block
        float m0 = 0.25f * (r0c0.x + r0c0.y + r1c0.x + r1c0.y);
        float m1 = 0.25f * (r0c1.x + r0c1.y + r1c1.x + r1c1.y);
        float m2 = 0.25f * (r0c2.x + r0c2.y + r1c2.x + r1c2.y);
        float m3 = 0.25f * (r0c3.x + r0c3.y + r1c3.x + r1c3.y);
        w.x = f2u(m0, m1); w.y = f2u(m2, m3);
        pyr2[1048576 + (by * 256 + bx) * 4 + t] = w;   // c_off[1]/4 = 1048576
    }
}

// ---------------------------------------------------------------------------
// Sample kernel (body identical to R12 best). 4 threads/query:
// xs = t>>1 (x0 vs x1 texel), cg = t&1 (channels 0-7 vs 8-15). Lane t loads
// bytes [16t,16t+16) of the 64B span [texel x0 | texel x1] for 4 (level,row)
// pairs -> 4 LDG.128 per thread. PDL: all setup before the grid-dependency
// sync, pyramid reads after. Accumulation in half2.
// ---------------------------------------------------------------------------
__device__ __forceinline__ void lvl_addr(int l, float gx, float gy, int t,
        const uint4*& r0, const uint4*& r1, float& fx, float& fy) {
    int   s  = 512 >> l;
    float fs = (float)(s - 1);
    float x = fminf(fmaxf((gx + 1.0f) * 0.5f * fs, 0.0f), fs);
    float y = fminf(fmaxf((gy + 1.0f) * 0.5f * fs, 0.0f), fs);
    int x0 = (int)x;             // trunc == floor (x >= 0)
    int y0 = (int)y;
    fx = x - (float)x0;          // 0 exactly when x1/y1 would clamp
    fy = y - (float)y0;
    const uint4* b = reinterpret_cast<const uint4*>(g_pyr + c_off[l]);
    r0 = b + (y0 * s + x0) * 2 + t;   // lane t: 16B chunk of the 64B x0|x1 span
    r1 = r0 + 2 * s;                  // row y0+1 (unclamped; weight 0 at edge)
}

__global__ void k_sample(const float* __restrict__ uv,
                         const float* __restrict__ p,
                         float* __restrict__ out, int N) {
    int idx = blockIdx.x * blockDim.x + threadIdx.x;
    int q = idx >> 2;
    if (q >= N) return;
    int t  = idx & 3;
    int xs = t >> 1;      // 0: x0 texel, 1: x1 texel
    int cg = t & 1;       // 0: channels 0-7, 1: channels 8-15

    float2 uvq = __ldg(reinterpret_cast<const float2*>(uv) + q);
    float  pp  = __ldg(&p[q]);

    float lf = pp * (float)(NLEV - 1);
    int   l0 = min((int)lf, NLEV - 1);
    int   l1 = min(l0 + 1, NLEV - 1);
    float alpha = lf - (float)l0;

    float gx = 2.0f * uvq.x - 1.0f;
    float gy = 2.0f * uvq.y - 1.0f;

    const uint4 *a0, *a1, *b0, *b1;
    float fxa, fya, fxb, fyb;
    lvl_addr(l0, gx, gy, t, a0, a1, fxa, fya);
    lvl_addr(l1, gx, gy, t, b0, b1, fxb, fyb);

    float wxa = xs ? fxa : (1.0f - fxa);
    float wxb = xs ? fxb : (1.0f - fxb);
    float la  = (1.0f - alpha) * wxa;
    float lb  = alpha * wxb;
    __half2 hw0 = __float2half2_rn(la * (1.0f - fya));
    __half2 hw1 = __float2half2_rn(la * fya);
    __half2 hw2 = __float2half2_rn(lb * (1.0f - fyb));
    __half2 hw3 = __float2half2_rn(lb * fyb);

    // PDL: wait for k_prep's writes to be visible, then read the pyramid.
#if __CUDA_ARCH__ >= 900
    cudaGridDependencySynchronize();
#endif

    // batch all 4 span loads (both levels, both rows)
    uint4 va0 = __ldg(a0);
    uint4 va1 = __ldg(a1);
    uint4 vb0 = __ldg(b0);
    uint4 vb1 = __ldg(b1);

    // half2 accumulation: 4 HMUL2 + 12 HFMA2, no per-texel converts
    __half2 A0 = __hmul2(u2h(va0.x), hw0);
    __half2 A1 = __hmul2(u2h(va0.y), hw0);
    __half2 A2 = __hmul2(u2h(va0.z), hw0);
    __half2 A3 = __hmul2(u2h(va0.w), hw0);
    A0 = __hfma2(u2h(va1.x), hw1, A0);
    A1 = __hfma2(u2h(va1.y), hw1, A1);
    A2 = __hfma2(u2h(va1.z), hw1, A2);
    A3 = __hfma2(u2h(va1.w), hw1, A3);
    A0 = __hfma2(u2h(vb0.x), hw2, A0);
    A1 = __hfma2(u2h(vb0.y), hw2, A1);
    A2 = __hfma2(u2h(vb0.z), hw2, A2);
    A3 = __hfma2(u2h(vb0.w), hw2, A3);
    A0 = __hfma2(u2h(vb1.x), hw3, A0);
    A1 = __hfma2(u2h(vb1.y), hw3, A1);
    A2 = __hfma2(u2h(vb1.z), hw3, A2);
    A3 = __hfma2(u2h(vb1.w), hw3, A3);

    // combine x0-side and x1-side partial sums (lane ^ 2)
    const unsigned FULL = 0xFFFFFFFFu;
    A0 = __hadd2(A0, u2h(__shfl_xor_sync(FULL, h2u(A0), 2)));
    A1 = __hadd2(A1, u2h(__shfl_xor_sync(FULL, h2u(A1), 2)));
    A2 = __hadd2(A2, u2h(__shfl_xor_sync(FULL, h2u(A2), 2)));
    A3 = __hadd2(A3, u2h(__shfl_xor_sync(FULL, h2u(A3), 2)));

    // lane (xs,cg) stores float4 slot cg*2+xs: xs=0 -> ch 8cg..+3 (A0,A1),
    // xs=1 -> ch 8cg+4..+7 (A2,A3)
    float2 f0 = __half22float2(xs ? A2 : A0);
    float2 f1 = __half22float2(xs ? A3 : A1);
    float4 r = make_float4(f0.x, f0.y, f1.x, f1.y);
    __stcs(reinterpret_cast<float4*>(out) + q * 4 + (cg * 2 + xs), r);
}

// ---------------------------------------------------------------------------
extern "C" void kernel_launch(void* const* d_in, const int* in_sizes, int n_in,
                              void* d_out, int out_size) {
    const float* uv  = (const float*)d_in[0];
    const float* p   = (const float*)d_in[1];
    const float* tex = (const float*)d_in[2];
    float* out = (float*)d_out;
    int N = in_sizes[1];          // number of queries (p element count)

    // mips-first (342 blocks) + 1024 transpose blocks
    k_prep<<<MIPS_BLOCKS + 1024, 256>>>(tex);

    // sample with programmatic dependent launch: overlaps its ramp/input
    // loads with prep's tail; correctness via cudaGridDependencySynchronize.
    int total = N * 4;
    cudaLaunchConfig_t cfg = {};
    cfg.gridDim  = dim3((total + 255) / 256);
    cfg.blockDim = dim3(256);
    cudaLaunchAttribute attr[1];
    attr[0].id = cudaLaunchAttributeProgrammaticStreamSerialization;
    attr[0].val.programmaticStreamSerializationAllowed = 1;
    cfg.attrs = attr;
    cfg.numAttrs = 1;
    cudaLaunchKernelEx(&cfg, k_sample, uv, p, out, N);
}